// round 11
// baseline (speedup 1.0000x reference)
#include <cuda_runtime.h>

// Problem constants (fixed shapes from reference)
#define NN 100000          // nodes
#define NE 3200000         // edges
#define KE 16              // 2 * K_EIG

// Scratch (device globals — no allocation allowed).
// dst/nd/rden: ~14 MB, written evict-normal -> L2-resident across passes.
// (ex lives in-place in the attn output slot of d_out.)
__device__ int    g_dst[NE];
__device__ float2 g_nd[NN];     // .x = numerator sum(ex*hx), .y = denom sum(ex)
__device__ float  g_rden[NN];   // 1 / (denom + 1e-16), precomputed once
__device__ int    g_is64;       // 1 if edge_index is int64, 0 if int32

// Init accumulators; thread 0 also detects edge_index dtype.
// True int64 indices are < 100000 -> high 32 bits of every u64 word are zero.
// int32 data reinterpreted as u64 has nonzero high half with prob ~1 per word.
__global__ void k_init(const unsigned long long* __restrict__ ei) {
    int i = blockIdx.x * blockDim.x + threadIdx.x;
    if (i == 0) {
        int is64 = 1;
        #pragma unroll
        for (int k = 0; k < 16; k++)
            if (ei[k] >> 32) { is64 = 0; break; }
        g_is64 = is64;
    }
    if (i < NN) g_nd[i] = make_float2(0.0f, 0.0f);
}

// Pass 1: per-edge logits -> pair_pred, ex=exp(score) (stored in-place into the
// attn output slot), and BOTH segment reductions: num[d] += ex*hx,
// denom[d] += ex (same float2 cache line).
// All streaming loads are front-batched (MLP ~10) so one DRAM round-trip
// covers every line this thread touches; FMA chains interleave behind it.
__global__ void __launch_bounds__(256) k_edge_score(
    const float* __restrict__ x,
    const void* __restrict__ ei_raw,    // [2, NE] int64 OR int32 (see g_is64)
    const float* __restrict__ ea,       // [NE, 16]
    const float* __restrict__ W,        // [1, 1]
    const float* __restrict__ Wn,       // [2, 2] row-major
    const float* __restrict__ We,       // [16, 2] row-major
    float* __restrict__ pp_out,         // [NE, 2]
    float* __restrict__ ex_out)         // [NE]  (= attn slot, holds ex for now)
{
    int e0 = (blockIdx.x * blockDim.x + threadIdx.x) * 2;
    if (e0 >= NE) return;

    // ---- Front-batched loads (issue everything before consuming) ----
    int s[2], d[2];
    if (g_is64) {
        const long long* ei = (const long long*)ei_raw;
        longlong2 sp = __ldcs((const longlong2*)(ei + e0));
        longlong2 dp = __ldcs((const longlong2*)(ei + NE + e0));
        s[0] = (int)sp.x; s[1] = (int)sp.y;
        d[0] = (int)dp.x; d[1] = (int)dp.y;
    } else {
        const int* ei = (const int*)ei_raw;
        int2 sp = __ldcs((const int2*)(ei + e0));
        int2 dp = __ldcs((const int2*)(ei + NE + e0));
        s[0] = sp.x; s[1] = sp.y;
        d[0] = dp.x; d[1] = dp.y;
    }

    // Both edges' attribute rows: 8x LDG.128, read-once -> evict-first
    const float4* row = (const float4*)(ea + (size_t)e0 * KE);
    float4 t[8];
    #pragma unroll
    for (int i = 0; i < 8; i++) t[i] = __ldcs(row + i);

    // Node feature gathers (x is 400 KB, L2-resident)
    float xsv[2] = { __ldg(x + s[0]), __ldg(x + s[1]) };
    float xdv[2] = { __ldg(x + d[0]), __ldg(x + d[1]) };

    // Uniform weight loads (L1 broadcast, kept in registers)
    float  w0 = __ldg(W);
    float4 wn = *(const float4*)Wn;   // (Wn00, Wn01, Wn10, Wn11)
    float w[32];
    #pragma unroll
    for (int i = 0; i < 8; i++) {
        float4 tw = ((const float4*)We)[i];
        w[4*i]   = tw.x; w[4*i+1] = tw.y; w[4*i+2] = tw.z; w[4*i+3] = tw.w;
    }

    // ---- Compute: 4 independent FMA chains (p0/p1 x 2 edges) ----
    float pp[4];
    float exv[2];
    float hxv[2];

    #pragma unroll
    for (int j = 0; j < 2; j++) {
        hxv[j] = xsv[j] * w0;
        float p0 = xsv[j] * wn.x + xdv[j] * wn.z;
        float p1 = xsv[j] * wn.y + xdv[j] * wn.w;
        #pragma unroll
        for (int i = 0; i < 4; i++) {
            float4 tt = t[4*j + i];
            p0 = fmaf(tt.x, w[8*i],     p0);
            p1 = fmaf(tt.x, w[8*i + 1], p1);
            p0 = fmaf(tt.y, w[8*i + 2], p0);
            p1 = fmaf(tt.y, w[8*i + 3], p1);
            p0 = fmaf(tt.z, w[8*i + 4], p0);
            p1 = fmaf(tt.z, w[8*i + 5], p1);
            p0 = fmaf(tt.w, w[8*i + 6], p0);
            p1 = fmaf(tt.w, w[8*i + 7], p1);
        }

        // leaky_relu(., 0.2)
        float pp0 = p0 > 0.0f ? p0 : 0.2f * p0;
        float pp1 = p1 > 0.0f ? p1 : 0.2f * p1;
        pp[2*j]   = pp0;
        pp[2*j+1] = pp1;

        // exp(score) without max-shift: expected |score| <~ 35 (sigma~6, max
        // over 3.2M edges ~5.2 sigma) << 88 (fp32 exp range); softmax ratio is
        // shift-invariant, residual rel err ~1e-6 vs 1e-3 tol. Clamp at 80 is
        // pure insurance: a numerical no-op for plausible data, but converts a
        // hypothetical inf/NaN blowup into a graceful saturated softmax.
        exv[j] = expf(fminf(pp0 - pp1, 80.0f));
    }

    // Write-only output: streaming store (no L2 residency claim)
    __stcs((float4*)(pp_out + 2 * e0), make_float4(pp[0], pp[1], pp[2], pp[3]));
    // Inter-pass data: default stores -> keep in L2 for pass 2
    *(float2*)(ex_out + e0) = make_float2(exv[0], exv[1]);
    *(int2*)(g_dst + e0)    = make_int2(d[0], d[1]);

    // Fused segment reductions (numerator + denominator, same cache line)
    atomicAdd(&g_nd[d[0]].x, exv[0] * hxv[0]);
    atomicAdd(&g_nd[d[0]].y, exv[0]);
    atomicAdd(&g_nd[d[1]].x, exv[1] * hxv[1]);
    atomicAdd(&g_nd[d[1]].y, exv[1]);
}

// Reciprocal precompute + node output. 100K divides instead of 3.2M:
// rden[i] = 1/(denom+1e-16); out[i] = num * rden (== num/(denom+eps) to 1 ulp).
__global__ void k_rcp_out(float* __restrict__ out) {
    int i = blockIdx.x * blockDim.x + threadIdx.x;
    if (i < NN) {
        float2 nd = g_nd[i];
        float r = 1.0f / (nd.y + 1e-16f);
        g_rden[i] = r;
        out[i] = nd.x * r;
    }
}

// Pass 2: attn = ex * rden[d], in place over the ex values. Pure FMUL —
// no MUFU. Gather footprint is the dense 400 KB rden array (L2-resident);
// ex/dst reads mostly L2 hits from pass 1 residency.
__global__ void __launch_bounds__(256) k_attn(float* __restrict__ attn) {
    int i = (blockIdx.x * blockDim.x + threadIdx.x) * 4;
    if (i >= NE) return;
    float4 ex = *(const float4*)(attn + i);
    int4   dd = *(const int4*)(g_dst + i);

    float a0 = ex.x * __ldg(g_rden + dd.x);
    float a1 = ex.y * __ldg(g_rden + dd.y);
    float a2 = ex.z * __ldg(g_rden + dd.z);
    float a3 = ex.w * __ldg(g_rden + dd.w);

    __stcs((float4*)(attn + i), make_float4(a0, a1, a2, a3));
}

extern "C" void kernel_launch(void* const* d_in, const int* in_sizes, int n_in,
                              void* d_out, int out_size) {
    const float* x  = (const float*)d_in[0];
    const void*  ei = d_in[1];
    const float* ea = (const float*)d_in[2];
    const float* W  = (const float*)d_in[3];
    const float* Wn = (const float*)d_in[4];
    const float* We = (const float*)d_in[5];

    float* out  = (float*)d_out;        // [NN]
    float* attn = out + NN;             // [NE]
    float* pp   = attn + NE;            // [NE, 2]

    k_init<<<(NN + 255) / 256, 256>>>((const unsigned long long*)ei);
    k_edge_score<<<NE / 2 / 256, 256>>>(x, ei, ea, W, Wn, We, pp, attn);
    k_rcp_out<<<(NN + 255) / 256, 256>>>(out);
    k_attn<<<NE / 4 / 256, 256>>>(attn);
}

// round 12
// speedup vs baseline: 1.7570x; 1.7570x over previous
#include <cuda_runtime.h>

// Problem constants (fixed shapes from reference)
#define NN 100000          // nodes
#define NE 3200000         // edges
#define KE 16              // 2 * K_EIG

// Scratch (device globals — no allocation allowed).
// dst/nd/rden: ~14 MB, written evict-normal -> L2-resident across passes.
// (ex lives in-place in the attn output slot of d_out.)
__device__ int    g_dst[NE];
__device__ float2 g_nd[NN];     // .x = numerator sum(ex*hx), .y = denom sum(ex)
__device__ float  g_rden[NN];   // 1 / (denom + 1e-16), precomputed once
__device__ int    g_is64;       // 1 if edge_index is int64, 0 if int32

// Init accumulators; thread 0 also detects edge_index dtype.
__global__ void k_init(const unsigned long long* __restrict__ ei) {
    int i = blockIdx.x * blockDim.x + threadIdx.x;
    if (i == 0) {
        int is64 = 1;
        #pragma unroll
        for (int k = 0; k < 16; k++)
            if (ei[k] >> 32) { is64 = 0; break; }
        g_is64 = is64;
    }
    if (i < NN) g_nd[i] = make_float2(0.0f, 0.0f);
}

// Pass 1: per-edge logits -> pair_pred, ex=exp(score) (in-place into the attn
// slot), and a single fused float2 vector atomic per edge:
// g_nd[d] += (ex*hx, ex). Scattered-op budget per edge: 2 gathers + 1 RED.
__global__ void __launch_bounds__(256) k_edge_score(
    const float* __restrict__ x,
    const void* __restrict__ ei_raw,    // [2, NE] int64 OR int32 (see g_is64)
    const float* __restrict__ ea,       // [NE, 16]
    const float* __restrict__ W,        // [1, 1]
    const float* __restrict__ Wn,       // [2, 2] row-major
    const float* __restrict__ We,       // [16, 2] row-major
    float* __restrict__ pp_out,         // [NE, 2]
    float* __restrict__ ex_out)         // [NE]  (= attn slot, holds ex for now)
{
    int e0 = (blockIdx.x * blockDim.x + threadIdx.x) * 2;
    if (e0 >= NE) return;

    // ---- Front-batched loads (issue everything before consuming) ----
    int s[2], d[2];
    if (g_is64) {
        const long long* ei = (const long long*)ei_raw;
        longlong2 sp = __ldcs((const longlong2*)(ei + e0));
        longlong2 dp = __ldcs((const longlong2*)(ei + NE + e0));
        s[0] = (int)sp.x; s[1] = (int)sp.y;
        d[0] = (int)dp.x; d[1] = (int)dp.y;
    } else {
        const int* ei = (const int*)ei_raw;
        int2 sp = __ldcs((const int2*)(ei + e0));
        int2 dp = __ldcs((const int2*)(ei + NE + e0));
        s[0] = sp.x; s[1] = sp.y;
        d[0] = dp.x; d[1] = dp.y;
    }

    // Both edges' attribute rows: 8x LDG.128, read-once -> evict-first
    const float4* row = (const float4*)(ea + (size_t)e0 * KE);
    float4 t[8];
    #pragma unroll
    for (int i = 0; i < 8; i++) t[i] = __ldcs(row + i);

    // Node feature gathers (scattered; L1tex wavefront cost dominates)
    float xsv[2] = { __ldg(x + s[0]), __ldg(x + s[1]) };
    float xdv[2] = { __ldg(x + d[0]), __ldg(x + d[1]) };

    // Uniform weight loads (L1 broadcast, kept in registers)
    float  w0 = __ldg(W);
    float4 wn = *(const float4*)Wn;   // (Wn00, Wn01, Wn10, Wn11)
    float w[32];
    #pragma unroll
    for (int i = 0; i < 8; i++) {
        float4 tw = ((const float4*)We)[i];
        w[4*i]   = tw.x; w[4*i+1] = tw.y; w[4*i+2] = tw.z; w[4*i+3] = tw.w;
    }

    // ---- Compute: 4 independent FMA chains (p0/p1 x 2 edges) ----
    float pp[4];
    float exv[2];
    float hxv[2];

    #pragma unroll
    for (int j = 0; j < 2; j++) {
        hxv[j] = xsv[j] * w0;
        float p0 = xsv[j] * wn.x + xdv[j] * wn.z;
        float p1 = xsv[j] * wn.y + xdv[j] * wn.w;
        #pragma unroll
        for (int i = 0; i < 4; i++) {
            float4 tt = t[4*j + i];
            p0 = fmaf(tt.x, w[8*i],     p0);
            p1 = fmaf(tt.x, w[8*i + 1], p1);
            p0 = fmaf(tt.y, w[8*i + 2], p0);
            p1 = fmaf(tt.y, w[8*i + 3], p1);
            p0 = fmaf(tt.z, w[8*i + 4], p0);
            p1 = fmaf(tt.z, w[8*i + 5], p1);
            p0 = fmaf(tt.w, w[8*i + 6], p0);
            p1 = fmaf(tt.w, w[8*i + 7], p1);
        }

        // leaky_relu(., 0.2)
        float pp0 = p0 > 0.0f ? p0 : 0.2f * p0;
        float pp1 = p1 > 0.0f ? p1 : 0.2f * p1;
        pp[2*j]   = pp0;
        pp[2*j+1] = pp1;

        // exp(score) without max-shift (|score| <~ 35 << 88; softmax ratio is
        // shift-invariant; measured rel_err 3e-7). Clamp 80 = NaN insurance.
        exv[j] = expf(fminf(pp0 - pp1, 80.0f));
    }

    // Write-only output: streaming store (no L2 residency claim)
    __stcs((float4*)(pp_out + 2 * e0), make_float4(pp[0], pp[1], pp[2], pp[3]));
    // Inter-pass data: default stores -> keep in L2 for pass 2
    *(float2*)(ex_out + e0) = make_float2(exv[0], exv[1]);
    *(int2*)(g_dst + e0)    = make_int2(d[0], d[1]);

    // ONE fused vector atomic per edge (RED.ADD.F32X2, sm_90+):
    // halves scattered atomic instructions/wavefronts vs two scalar REDs.
    atomicAdd(&g_nd[d[0]], make_float2(exv[0] * hxv[0], exv[0]));
    atomicAdd(&g_nd[d[1]], make_float2(exv[1] * hxv[1], exv[1]));
}

// Reciprocal precompute + node output. 100K divides instead of 3.2M:
// rden[i] = 1/(denom+1e-16); out[i] = num * rden (== num/(denom+eps) to 1 ulp).
__global__ void k_rcp_out(float* __restrict__ out) {
    int i = blockIdx.x * blockDim.x + threadIdx.x;
    if (i < NN) {
        float2 nd = g_nd[i];
        float r = 1.0f / (nd.y + 1e-16f);
        g_rden[i] = r;
        out[i] = nd.x * r;
    }
}

// Pass 2: attn = ex * rden[d], in place over the ex values. Pure FMUL.
// Measured: DRAM 13.6% (L2 residency confirmed), L1tex 65% = wavefront-bound
// on the rden gather — irreducible without edge reordering.
__global__ void __launch_bounds__(256) k_attn(float* __restrict__ attn) {
    int i = (blockIdx.x * blockDim.x + threadIdx.x) * 4;
    if (i >= NE) return;
    float4 ex = *(const float4*)(attn + i);
    int4   dd = *(const int4*)(g_dst + i);

    float a0 = ex.x * __ldg(g_rden + dd.x);
    float a1 = ex.y * __ldg(g_rden + dd.y);
    float a2 = ex.z * __ldg(g_rden + dd.z);
    float a3 = ex.w * __ldg(g_rden + dd.w);

    __stcs((float4*)(attn + i), make_float4(a0, a1, a2, a3));
}

extern "C" void kernel_launch(void* const* d_in, const int* in_sizes, int n_in,
                              void* d_out, int out_size) {
    const float* x  = (const float*)d_in[0];
    const void*  ei = d_in[1];
    const float* ea = (const float*)d_in[2];
    const float* W  = (const float*)d_in[3];
    const float* Wn = (const float*)d_in[4];
    const float* We = (const float*)d_in[5];

    float* out  = (float*)d_out;        // [NN]
    float* attn = out + NN;             // [NE]
    float* pp   = attn + NE;            // [NE, 2]

    k_init<<<(NN + 255) / 256, 256>>>((const unsigned long long*)ei);
    k_edge_score<<<NE / 2 / 256, 256>>>(x, ei, ea, W, Wn, We, pp, attn);
    k_rcp_out<<<(NN + 255) / 256, 256>>>(out);
    k_attn<<<NE / 4 / 256, 256>>>(attn);
}